// round 9
// baseline (speedup 1.0000x reference)
#include <cuda_runtime.h>
#include <cuda_fp16.h>
#include <cstdint>
#include <cstddef>

#define VOCAB   50000
#define VPAD    50048        // 391 * 128
#define XS      300
#define HS      150
#define HS3     450
#define NPACK   600          // [iou(450) | f(150)]
#define NBROW   768
#define NC      5
#define DEPTH   18
#define NNODES  524287
#define LEAVES  262144
#define KPW     320
#define KPU     160
#define LVL_GEMM 10          // levels >= this use the HMMA path
#define LTOP     9           // persistent kernel covers levels LTOP..0
#define UGRID    512

// ---------------- static device scratch ------------------------------------------
__device__ __half g_EW[(size_t)VOCAB * NPACK];            // emb @ [W|bias] (bias folded)
__device__ __half g_hiou[(size_t)(LEAVES / 2) * HS3];
__device__ __half g_hUf[(size_t)LEAVES * HS];
__device__ float  g_c[(size_t)NNODES * HS];
__device__ __half g_hf[(size_t)(NNODES + 128) * KPU];
__device__ __half g_sf[(size_t)(LEAVES / 2) * KPU];
__device__ __half g_Ef[(size_t)VPAD * KPW];
__device__ __half g_Bw[(size_t)NBROW * KPW];
__device__ __half g_Bu[(size_t)NBROW * KPU];
__device__ int    g_bar;

// ---------------- helpers ---------------------------------------------------------
__device__ __forceinline__ uint32_t smem_u32(const void* p) {
    uint32_t a;
    asm("{ .reg .u64 t; cvta.to.shared.u64 t, %1; cvt.u32.u64 %0, t; }" : "=r"(a) : "l"(p));
    return a;
}
#define CP16(dst, src) \
    asm volatile("cp.async.cg.shared.global [%0], [%1], 16;" :: "r"(dst), "l"(src))
#define CP_COMMIT() asm volatile("cp.async.commit_group;" ::: "memory")
#define CP_WAITG2() asm volatile("cp.async.wait_group 2;" ::: "memory")
#define CP_WAIT0()  asm volatile("cp.async.wait_group 0;" ::: "memory")
#define LDSM4(r0, r1, r2, r3, addr)                                               \
    asm volatile("ldmatrix.sync.aligned.m8n8.x4.shared.b16 {%0,%1,%2,%3}, [%4];"  \
                 : "=r"(r0), "=r"(r1), "=r"(r2), "=r"(r3) : "r"(addr))
#define MMA_F16(d, a0, a1, a2, a3, b0, b1)                                       \
    asm volatile("mma.sync.aligned.m16n8k16.row.col.f32.f16.f16.f32 "            \
                 "{%0,%1,%2,%3},{%4,%5,%6,%7},{%8,%9},{%0,%1,%2,%3};"            \
                 : "+f"(d[0]), "+f"(d[1]), "+f"(d[2]), "+f"(d[3])                \
                 : "r"(a0), "r"(a1), "r"(a2), "r"(a3), "r"(b0), "r"(b1))

// ---------------- FMA-only activations -------------------------------------------
__device__ __forceinline__ float sig_f(float x) {
    float ax = fabsf(x);
    if (ax > 1.0f) return 1.0f / (1.0f + __expf(-x));
    float x2 = x * x;
    float p = fmaf(x2, 2.1357958e-5f, -2.1081349e-4f);
    p = fmaf(x2, p, 2.0833333e-3f);
    p = fmaf(x2, p, -2.0833333e-2f);
    p = fmaf(x2, p, 0.25f);
    return fmaf(x, p, 0.5f);
}
__device__ __forceinline__ float tanh_f(float x) {
    float ax = fabsf(x);
    if (ax > 0.55f) {
        float t = __expf(-2.0f * ax);
        float r = __fdividef(1.0f - t, 1.0f + t);
        return x < 0.0f ? -r : r;
    }
    float x2 = x * x;
    float p = fmaf(x2, 2.1869488e-2f, -5.3968254e-2f);
    p = fmaf(x2, p, 1.3333333e-1f);
    p = fmaf(x2, p, -3.3333333e-1f);
    p = fmaf(x2, p, 1.0f);
    return x * p;
}

// ---------------- prep kernels ----------------------------------------------------
// Bias fold: A (emb) gets a 1.0 column at k==XS; Bw row n gets bias at k==XS.
__global__ void k_prep_w(const float* __restrict__ Wiou, const float* __restrict__ Wf,
                         const float* __restrict__ Uiou, const float* __restrict__ Uf,
                         const float* __restrict__ biou, const float* __restrict__ bf)
{
    int idx = blockIdx.x * blockDim.x + threadIdx.x;
    const int NW = NBROW * KPW;
    const int NU = NBROW * KPU;
    if (idx < NW) {
        int n = idx / KPW, k = idx - n * KPW;
        float v = 0.0f;
        if (n < NPACK) {
            if (k < XS)       v = (n < HS3) ? Wiou[k * HS3 + n] : Wf[k * HS + (n - HS3)];
            else if (k == XS) v = (n < HS3) ? biou[n] : bf[n - HS3];
        }
        g_Bw[idx] = __float2half_rn(v);
    } else if (idx < NW + NU) {
        int j = idx - NW;
        int n = j / KPU, k = j - n * KPU;
        float v = 0.0f;
        if (k < HS && n < NPACK) v = (n < HS3) ? Uiou[k * HS3 + n] : Uf[k * HS + (n - HS3)];
        g_Bu[j] = __float2half_rn(v);
    }
}

__global__ void k_prep_emb(const float* __restrict__ emb)
{
    int idx = blockIdx.x * blockDim.x + threadIdx.x;
    if (idx >= VPAD * KPW) return;
    int r = idx / KPW, k = idx - r * KPW;
    float v = 0.0f;
    if (r < VOCAB) {
        if (k < XS)       v = emb[(size_t)r * XS + k];
        else if (k == XS) v = 1.0f;          // bias slot
    }
    g_Ef[idx] = __float2half_rn(v);
}

__global__ void k_zeropads()
{
    int idx = blockIdx.x * blockDim.x + threadIdx.x;
    const int T1 = (NNODES + 128) * 10;
    const int T2 = (LEAVES / 2) * 10;
    if (idx < T1) {
        int r = idx / 10, k = HS + idx % 10;
        g_hf[(size_t)r * KPU + k] = __float2half_rn(0.0f);
    } else if (idx < T1 + T2) {
        int j = idx - T1;
        int r = j / 10, k = HS + j % 10;
        g_sf[(size_t)r * KPU + k] = __float2half_rn(0.0f);
    }
}

__global__ void k_bar_reset() { g_bar = 0; }

// ---------------- vocab GEMM: 4-stage cp.async pipeline (K=320) -------------------
#define PLANEB 10240                  // 128 rows * 80B (chunked path)
#define STAGEB 20480
#define NSTAGE 4
#define SMEMT  (NSTAGE * STAGEB)      // 81920

__global__ __launch_bounds__(256, 2)
void k_mma_g(const __half* __restrict__ A, int M, int Kpad,
             const __half* __restrict__ B, int Nact, __half* __restrict__ C, int ldc)
{
    extern __shared__ char smem[];
    const uint32_t sb = smem_u32(smem);
    const int tid  = threadIdx.x;
    const int lane = tid & 31;
    const int wid  = tid >> 5;
    const int row0 = blockIdx.y << 7;
    const int col0 = blockIdx.x << 7;
    const int m0 = (wid & 3) << 5;
    const int n0 = (wid >> 2) << 6;
    const int g   = lane >> 2;
    const int tig = lane & 3;

    const int lr   = lane & 7;
    const uint32_t aOff = (uint32_t)(m0 + lr + (((lane >> 3) & 1) << 3)) * 80
                        + (uint32_t)((lane >> 4) << 4);
    const uint32_t bOff = (uint32_t)(n0 + lr + ((lane >> 4) << 3)) * 80
                        + (uint32_t)(((lane >> 3) & 1) << 4);

    const char* pA = (const char*)(A + (size_t)row0 * Kpad);
    const char* pB = (const char*)(B + (size_t)col0 * Kpad);

    const int r_ld = tid >> 1;
    const int sg2  = (tid & 1) << 1;

    float d[2][8][4];
    #pragma unroll
    for (int mb = 0; mb < 2; mb++)
        #pragma unroll
        for (int nb = 0; nb < 8; nb++)
            #pragma unroll
            for (int q = 0; q < 4; q++) d[mb][nb][q] = 0.0f;

    auto load_chunk = [&](int kb, int st) {
        uint32_t dbase = sb + st * STAGEB + r_ld * 80 + sg2 * 16;
        size_t   soff  = ((size_t)r_ld * Kpad + kb + sg2 * 8) * 2;
        CP16(dbase,               pA + soff);
        CP16(dbase + 16,          pA + soff + 16);
        CP16(dbase + PLANEB,      pB + soff);
        CP16(dbase + PLANEB + 16, pB + soff + 16);
    };

    const int chunks = Kpad >> 5;
    #pragma unroll
    for (int s = 0; s < NSTAGE - 1; s++) {
        load_chunk(s << 5, s);
        CP_COMMIT();
    }

    for (int c = 0; c < chunks; c++) {
        CP_WAITG2();
        __syncthreads();

        const uint32_t sbase = sb + (c & (NSTAGE - 1)) * STAGEB;

        #pragma unroll
        for (int ks = 0; ks < 2; ks++) {
            uint32_t ah[2][4];
            #pragma unroll
            for (int mb = 0; mb < 2; mb++) {
                uint32_t aoff = sbase + aOff + mb * (16 * 80) + ks * 32;
                LDSM4(ah[mb][0], ah[mb][1], ah[mb][2], ah[mb][3], aoff);
            }
            #pragma unroll
            for (int pr = 0; pr < 4; pr++) {
                uint32_t boff = sbase + PLANEB + bOff + pr * (16 * 80) + ks * 32;
                uint32_t bh[4];
                LDSM4(bh[0], bh[1], bh[2], bh[3], boff);
                #pragma unroll
                for (int mb = 0; mb < 2; mb++) {
                    MMA_F16(d[mb][2 * pr],     ah[mb][0], ah[mb][1], ah[mb][2], ah[mb][3], bh[0], bh[1]);
                    MMA_F16(d[mb][2 * pr + 1], ah[mb][0], ah[mb][1], ah[mb][2], ah[mb][3], bh[2], bh[3]);
                }
            }
        }
        __syncthreads();
        if (c + NSTAGE - 1 < chunks)
            load_chunk((c + NSTAGE - 1) << 5, (c + NSTAGE - 1) & (NSTAGE - 1));
        CP_COMMIT();
    }

    #pragma unroll
    for (int mb = 0; mb < 2; mb++) {
        int gr = row0 + m0 + mb * 16 + g;
        #pragma unroll
        for (int nb = 0; nb < 8; nb++) {
            int gc = col0 + n0 + nb * 8 + tig * 2;
            if (gc < Nact) {
                if (gr < M)
                    *(__half2*)(C + (size_t)gr * ldc + gc) =
                        __floats2half2_rn(d[mb][nb][0], d[mb][nb][1]);
                if (gr + 8 < M)
                    *(__half2*)(C + (size_t)(gr + 8) * ldc + gc) =
                        __floats2half2_rn(d[mb][nb][2], d[mb][nb][3]);
            }
        }
    }
}

// ---------------- level GEMM: monolithic K=160, single sync -----------------------
#define LROW   336                    // 320B data + 16B pad
#define LPLANE (128 * 336)            // 43008
#define LSMEM  (2 * LPLANE)           // 86016

__global__ __launch_bounds__(256, 2)
void k_mma_lvl(const __half* __restrict__ A1, int M1, __half* __restrict__ C1,
               const __half* __restrict__ A2, int M2, __half* __restrict__ C2,
               const __half* __restrict__ Bu, int nby1)
{
    extern __shared__ char smem[];
    const uint32_t sb = smem_u32(smem);

    const __half* A; const __half* B; __half* C;
    int ldc, Nact, bx, by;
    {
        int b = blockIdx.x;
        int total1 = nby1 << 2;
        if (b < total1) {
            A = A1; C = C1; ldc = HS3; Nact = HS3; B = Bu;
            bx = b & 3; by = b >> 2;
        } else {
            b -= total1;
            A = A2; C = C2; ldc = HS; Nact = HS; B = Bu + (size_t)HS3 * KPU;
            bx = b & 1; by = b >> 1;
        }
    }
    const int tid  = threadIdx.x;
    const int lane = tid & 31;
    const int wid  = tid >> 5;
    const int row0 = by << 7;
    const int col0 = bx << 7;
    const int m0 = (wid & 3) << 5;
    const int n0 = (wid >> 2) << 6;
    const int g   = lane >> 2;
    const int tig = lane & 3;

    // full-tile load: A 128x160 halfs, B 128x160 halfs
    {
        const char* pA = (const char*)(A + (size_t)row0 * KPU);
        const char* pB = (const char*)(B + (size_t)col0 * KPU);
        int r  = tid >> 1;
        int hh = (tid & 1) * 160;
        uint32_t dst = sb + r * LROW + hh;
        size_t   src = (size_t)r * 320 + hh;
        #pragma unroll
        for (int i = 0; i < 10; i++) {
            CP16(dst + i * 16,          pA + src + i * 16);
            CP16(dst + LPLANE + i * 16, pB + src + i * 16);
        }
        CP_COMMIT();
    }
    CP_WAIT0();
    __syncthreads();

    float d[2][8][4];
    #pragma unroll
    for (int mb = 0; mb < 2; mb++)
        #pragma unroll
        for (int nb = 0; nb < 8; nb++)
            #pragma unroll
            for (int q = 0; q < 4; q++) d[mb][nb][q] = 0.0f;

    const int lr = lane & 7;
    const uint32_t aBase = sb + (uint32_t)(m0 + lr + (((lane >> 3) & 1) << 3)) * LROW
                         + (uint32_t)((lane >> 4) << 4);
    const uint32_t bBase = sb + LPLANE + (uint32_t)(n0 + lr + ((lane >> 4) << 3)) * LROW
                         + (uint32_t)(((lane >> 3) & 1) << 4);

    #pragma unroll
    for (int ks = 0; ks < 10; ks++) {
        uint32_t ah[2][4];
        #pragma unroll
        for (int mb = 0; mb < 2; mb++) {
            LDSM4(ah[mb][0], ah[mb][1], ah[mb][2], ah[mb][3],
                  aBase + mb * (16 * LROW) + ks * 32);
        }
        #pragma unroll
        for (int pr = 0; pr < 4; pr++) {
            uint32_t bh[4];
            LDSM4(bh[0], bh[1], bh[2], bh[3], bBase + pr * (16 * LROW) + ks * 32);
            #pragma unroll
            for (int mb = 0; mb < 2; mb++) {
                MMA_F16(d[mb][2 * pr],     ah[mb][0], ah[mb][1], ah[mb][2], ah[mb][3], bh[0], bh[1]);
                MMA_F16(d[mb][2 * pr + 1], ah[mb][0], ah[mb][1], ah[mb][2], ah[mb][3], bh[2], bh[3]);
            }
        }
    }

    #pragma unroll
    for (int mb = 0; mb < 2; mb++) {
        int gr = row0 + m0 + mb * 16 + g;
        #pragma unroll
        for (int nb = 0; nb < 8; nb++) {
            int gc = col0 + n0 + nb * 8 + tig * 2;
            if (gc < Nact) {
                *(__half2*)(C + (size_t)gr * ldc + gc) =
                    __floats2half2_rn(d[mb][nb][0], d[mb][nb][1]);
                *(__half2*)(C + (size_t)(gr + 8) * ldc + gc) =
                    __floats2half2_rn(d[mb][nb][2], d[mb][nb][3]);
            }
        }
    }
}

// ---------------- leaf level: gates + fused pair-sum + fused out ------------------
__global__ __launch_bounds__(320)
void k_leaf(const int* __restrict__ xid,
            const float* __restrict__ Wout, const float* __restrict__ bout,
            float* __restrict__ out)
{
    __shared__ float sh[300];
    const int t = threadIdx.x;
    const int b = blockIdx.x;
    if (t < 300) {
        int child = (t >= 150);
        int j = t - child * 150;
        int i = 2 * b + child;
        int n = (LEAVES - 1) + i;
        const __half* ew = g_EW + (size_t)xid[n] * NPACK;
        float iv = __half2float(ew[j]);
        float ov = __half2float(ew[HS + j]);
        float uv = __half2float(ew[2 * HS + j]);
        float cv = sig_f(iv) * tanh_f(uv);
        float hv = sig_f(ov) * tanh_f(cv);
        g_c[(size_t)n * HS + j] = cv;
        g_hf[(size_t)n * KPU + j] = __float2half_rn(hv);
        sh[t] = hv;
    }
    __syncthreads();
    if (t < 150) {
        float s = sh[t] + sh[150 + t];
        g_sf[(size_t)b * KPU + t] = __float2half_rn(s);
    }
    int w = t >> 5, lane = t & 31;
    if (w < 10) {
        int nd = w / 5, q = w - nd * 5;
        float a = 0.f;
        for (int j = lane; j < HS; j += 32)
            a = fmaf(sh[nd * HS + j], Wout[j * NC + q], a);
        #pragma unroll
        for (int off = 16; off; off >>= 1) a += __shfl_xor_sync(0xffffffffu, a, off);
        if (lane == 0) {
            int n = (LEAVES - 1) + 2 * b + nd;
            out[(size_t)n * NC + q] = a + bout[q];
        }
    }
}

// ---------------- internal-level combine + fused pair-sum + fused out -------------
__global__ __launch_bounds__(320)
void k_combine(int s, int cs, const int* __restrict__ xid,
               const float* __restrict__ Wout, const float* __restrict__ bout,
               float* __restrict__ out)
{
    __shared__ float sh[300];
    const int t = threadIdx.x;
    const int b = blockIdx.x;
    if (t < 300) {
        int child = (t >= 150);
        int j = t - child * 150;
        int k = 2 * b + child;
        int p = s + k;
        const __half* ew  = g_EW + (size_t)xid[p] * NPACK;
        const __half* hio = g_hiou + (size_t)k * HS3;
        float iv = __half2float(ew[j])          + __half2float(hio[j]);
        float ov = __half2float(ew[HS + j])     + __half2float(hio[HS + j]);
        float uv = __half2float(ew[2 * HS + j]) + __half2float(hio[2 * HS + j]);
        float xf = __half2float(ew[HS3 + j]);
        float fl = sig_f(xf + __half2float(g_hUf[(size_t)(2 * k) * HS + j]));
        float fr = sig_f(xf + __half2float(g_hUf[(size_t)(2 * k + 1) * HS + j]));
        float cl = g_c[(size_t)(cs + 2 * k) * HS + j];
        float cr = g_c[(size_t)(cs + 2 * k + 1) * HS + j];
        float cv = sig_f(iv) * tanh_f(uv) + fl * cl + fr * cr;
        float hv = sig_f(ov) * tanh_f(cv);
        g_c[(size_t)p * HS + j] = cv;
        g_hf[(size_t)p * KPU + j] = __float2half_rn(hv);
        sh[t] = hv;
    }
    __syncthreads();
    if (t < 150) {
        float sum = sh[t] + sh[150 + t];
        g_sf[(size_t)b * KPU + t] = __float2half_rn(sum);
    }
    int w = t >> 5, lane = t & 31;
    if (w < 10) {
        int nd = w / 5, q = w - nd * 5;
        float a = 0.f;
        for (int j = lane; j < HS; j += 32)
            a = fmaf(sh[nd * HS + j], Wout[j * NC + q], a);
        #pragma unroll
        for (int off = 16; off; off >>= 1) a += __shfl_xor_sync(0xffffffffu, a, off);
        if (lane == 0) {
            int p = s + 2 * b + nd;
            out[(size_t)p * NC + q] = a + bout[q];
        }
    }
}

// ---------------- persistent upper tree (levels LTOP..0) --------------------------
// 512 blocks x 256 threads; one node per block per level; software grid barrier.
__global__ __launch_bounds__(256, 4)
void k_upper(const float* __restrict__ Uiou, const float* __restrict__ Uf,
             const int* __restrict__ xid,
             const float* __restrict__ Wout, const float* __restrict__ bout,
             float* __restrict__ out)
{
    __shared__ float hl_[HS], hr_[HS], hs_[HS], ho_[HS];
    __shared__ float io_[HS3], fl_[HS], fr_[HS];
    const int t = threadIdx.x;
    const int k = blockIdx.x;
    int target = 0;

    for (int lvl = LTOP; lvl >= 0; lvl--) {
        const int M  = 1 << lvl;
        const int s  = M - 1;
        const int cs = 2 * M - 1;
        if (k < M) {
            const int p = s + k;
            for (int j = t; j < HS; j += 256) {
                float hl = __half2float(__ldcg(&g_hf[(size_t)(cs + 2 * k) * KPU + j]));
                float hr = __half2float(__ldcg(&g_hf[(size_t)(cs + 2 * k + 1) * KPU + j]));
                hl_[j] = hl; hr_[j] = hr; hs_[j] = hl + hr;
            }
            __syncthreads();

            for (int j = t; j < HS3; j += 256) {
                float a = 0.0f;
                #pragma unroll 5
                for (int kk = 0; kk < HS; kk++) a = fmaf(hs_[kk], Uiou[kk * HS3 + j], a);
                io_[j] = a;
            }
            for (int j = t; j < HS; j += 256) {
                float al = 0.0f, ar = 0.0f;
                #pragma unroll 5
                for (int kk = 0; kk < HS; kk++) {
                    float u = Uf[kk * HS + j];
                    al = fmaf(hl_[kk], u, al);
                    ar = fmaf(hr_[kk], u, ar);
                }
                fl_[j] = al; fr_[j] = ar;
            }
            __syncthreads();

            if (t < HS) {
                int j = t;
                const __half* ew = g_EW + (size_t)xid[p] * NPACK;
                float iv = __half2float(ew[j]) + io_[j];
                float ov = __half2float(ew[HS + j]) + io_[HS + j];
                float uv = __half2float(ew[2 * HS + j]) + io_[2 * HS + j];
                float xf = __half2float(ew[HS3 + j]);
                float fl = sig_f(xf + fl_[j]);
                float fr = sig_f(xf + fr_[j]);
                float cl = __ldcg(&g_c[(size_t)(cs + 2 * k) * HS + j]);
                float cr = __ldcg(&g_c[(size_t)(cs + 2 * k + 1) * HS + j]);
                float cv = sig_f(iv) * tanh_f(uv) + fl * cl + fr * cr;
                float hv = sig_f(ov) * tanh_f(cv);
                g_c[(size_t)p * HS + j] = cv;
                g_hf[(size_t)p * KPU + j] = __float2half_rn(hv);
                ho_[j] = hv;
            }
            __syncthreads();
            int w = t >> 5, lane = t & 31;
            if (w < NC) {
                float a = 0.f;
                for (int j = lane; j < HS; j += 32)
                    a = fmaf(ho_[j], Wout[j * NC + w], a);
                #pragma unroll
                for (int off = 16; off; off >>= 1) a += __shfl_xor_sync(0xffffffffu, a, off);
                if (lane == 0) out[(size_t)p * NC + w] = a + bout[w];
            }
        }
        // grid barrier (skip after last level)
        if (lvl == 0) break;
        __threadfence();
        __syncthreads();
        target += (int)gridDim.x;
        if (t == 0) {
            atomicAdd(&g_bar, 1);
            while (*((volatile int*)&g_bar) < target) { }
        }
        __syncthreads();
    }
}

// ---------------- host orchestration ---------------------------------------------
extern "C" void kernel_launch(void* const* d_in, const int* in_sizes, int n_in,
                              void* d_out, int out_size)
{
    (void)in_sizes; (void)n_in; (void)out_size;
    const int*   xid  = (const int*)d_in[0];
    const float* emb  = (const float*)d_in[1];
    const float* Wiou = (const float*)d_in[2];
    const float* Uiou = (const float*)d_in[3];
    const float* biou = (const float*)d_in[4];
    const float* Wf   = (const float*)d_in[5];
    const float* Uf   = (const float*)d_in[6];
    const float* bf   = (const float*)d_in[7];
    const float* Wout = (const float*)d_in[8];
    const float* bout = (const float*)d_in[9];
    float* out = (float*)d_out;

    __half *pEW, *pHiou, *pHUf, *pEf, *pBw, *pBu, *pHf, *pSf;
    cudaGetSymbolAddress((void**)&pEW,   g_EW);
    cudaGetSymbolAddress((void**)&pHiou, g_hiou);
    cudaGetSymbolAddress((void**)&pHUf,  g_hUf);
    cudaGetSymbolAddress((void**)&pEf,   g_Ef);
    cudaGetSymbolAddress((void**)&pBw,   g_Bw);
    cudaGetSymbolAddress((void**)&pBu,   g_Bu);
    cudaGetSymbolAddress((void**)&pHf,   g_hf);
    cudaGetSymbolAddress((void**)&pSf,   g_sf);

    cudaFuncSetAttribute(k_mma_g,   cudaFuncAttributeMaxDynamicSharedMemorySize, SMEMT);
    cudaFuncSetAttribute(k_mma_lvl, cudaFuncAttributeMaxDynamicSharedMemorySize, LSMEM);

    const dim3 thr(256);
    k_prep_w<<<(NBROW * KPW + NBROW * KPU + 255) / 256, thr>>>(Wiou, Wf, Uiou, Uf, biou, bf);
    k_prep_emb<<<(VPAD * KPW + 255) / 256, thr>>>(emb);
    {
        int zt = (NNODES + 128) * 10 + (LEAVES / 2) * 10;
        k_zeropads<<<(zt + 255) / 256, thr>>>();
    }

    // Vocab precompute (bias folded): g_EW = [emb|1] @ [W|b]^T
    k_mma_g<<<dim3(5, VPAD / 128), thr, SMEMT>>>(pEf, VOCAB, KPW, pBw, NPACK, pEW, NPACK);

    // Leaf level.
    k_leaf<<<LEAVES / 2, 320>>>(xid, Wout, bout, out);

    // Levels 17..10: monolithic-K HMMA GEMM + combine.
    for (int lvl = DEPTH - 1; lvl >= LVL_GEMM; lvl--) {
        int M  = 1 << lvl;
        int s  = M - 1;
        int cs = 2 * M - 1;
        int nby1 = M >> 7;        // exact (M >= 1024)
        int nby2 = M >> 6;
        int nblk = 4 * nby1 + 2 * nby2;
        k_mma_lvl<<<nblk, thr, LSMEM>>>(
            pSf, M, pHiou,
            pHf + (size_t)cs * KPU, 2 * M, pHUf,
            pBu, nby1);
        k_combine<<<M / 2, 320>>>(s, cs, xid, Wout, bout, out);
    }

    // Levels 9..0: single persistent kernel with software grid barrier.
    k_bar_reset<<<1, 1>>>();
    k_upper<<<UGRID, thr>>>(Uiou, Uf, xid, Wout, bout, out);
}

// round 10
// speedup vs baseline: 1.1372x; 1.1372x over previous
#include <cuda_runtime.h>
#include <cuda_fp16.h>
#include <cstdint>
#include <cstddef>

#define VOCAB   50000
#define VPAD    50048        // 391 * 128
#define XS      300
#define HS      150
#define HS3     450
#define NPACK   600          // [iou(450) | f(150)]
#define NBROW   768
#define NC      5
#define DEPTH   18
#define NNODES  524287
#define LEAVES  262144
#define KPW     320
#define KPU     160
#define LVL_SMALL 7          // levels >= this use the HMMA GEMM path
#define LTOP      6          // persistent kernel covers levels LTOP..0
#define UGRID     64

// ---------------- static device scratch ------------------------------------------
__device__ __half g_EW[(size_t)VOCAB * NPACK];            // [emb|1] @ [W|b] (bias folded)
__device__ __half g_hiou[(size_t)(LEAVES / 2) * HS3];
__device__ __half g_hUf[(size_t)LEAVES * HS];
__device__ float  g_c[(size_t)NNODES * HS];
__device__ __half g_hf[(size_t)(NNODES + 128) * KPU];
__device__ __half g_sf[(size_t)(LEAVES / 2) * KPU];
__device__ __half g_Ef[(size_t)VPAD * KPW];
__device__ __half g_Bw[(size_t)NBROW * KPW];
__device__ __half g_Bu[(size_t)NBROW * KPU];
__device__ int    g_bar;

// ---------------- helpers ---------------------------------------------------------
__device__ __forceinline__ uint32_t smem_u32(const void* p) {
    uint32_t a;
    asm("{ .reg .u64 t; cvta.to.shared.u64 t, %1; cvt.u32.u64 %0, t; }" : "=r"(a) : "l"(p));
    return a;
}
#define CP16(dst, src) \
    asm volatile("cp.async.cg.shared.global [%0], [%1], 16;" :: "r"(dst), "l"(src))
#define CP_COMMIT() asm volatile("cp.async.commit_group;" ::: "memory")
#define CP_WAITG2() asm volatile("cp.async.wait_group 2;" ::: "memory")
#define LDSM4(r0, r1, r2, r3, addr)                                               \
    asm volatile("ldmatrix.sync.aligned.m8n8.x4.shared.b16 {%0,%1,%2,%3}, [%4];"  \
                 : "=r"(r0), "=r"(r1), "=r"(r2), "=r"(r3) : "r"(addr))
#define MMA_F16(d, a0, a1, a2, a3, b0, b1)                                       \
    asm volatile("mma.sync.aligned.m16n8k16.row.col.f32.f16.f16.f32 "            \
                 "{%0,%1,%2,%3},{%4,%5,%6,%7},{%8,%9},{%0,%1,%2,%3};"            \
                 : "+f"(d[0]), "+f"(d[1]), "+f"(d[2]), "+f"(d[3])                \
                 : "r"(a0), "r"(a1), "r"(a2), "r"(a3), "r"(b0), "r"(b1))

// ---------------- FMA-only activations -------------------------------------------
__device__ __forceinline__ float sig_f(float x) {
    float ax = fabsf(x);
    if (ax > 1.0f) return 1.0f / (1.0f + __expf(-x));
    float x2 = x * x;
    float p = fmaf(x2, 2.1357958e-5f, -2.1081349e-4f);
    p = fmaf(x2, p, 2.0833333e-3f);
    p = fmaf(x2, p, -2.0833333e-2f);
    p = fmaf(x2, p, 0.25f);
    return fmaf(x, p, 0.5f);
}
__device__ __forceinline__ float tanh_f(float x) {
    float ax = fabsf(x);
    if (ax > 0.55f) {
        float t = __expf(-2.0f * ax);
        float r = __fdividef(1.0f - t, 1.0f + t);
        return x < 0.0f ? -r : r;
    }
    float x2 = x * x;
    float p = fmaf(x2, 2.1869488e-2f, -5.3968254e-2f);
    p = fmaf(x2, p, 1.3333333e-1f);
    p = fmaf(x2, p, -3.3333333e-1f);
    p = fmaf(x2, p, 1.0f);
    return x * p;
}

// ---------------- prep kernels ----------------------------------------------------
__global__ void k_prep_w(const float* __restrict__ Wiou, const float* __restrict__ Wf,
                         const float* __restrict__ Uiou, const float* __restrict__ Uf,
                         const float* __restrict__ biou, const float* __restrict__ bf)
{
    int idx = blockIdx.x * blockDim.x + threadIdx.x;
    const int NW = NBROW * KPW;
    const int NU = NBROW * KPU;
    if (idx < NW) {
        int n = idx / KPW, k = idx - n * KPW;
        float v = 0.0f;
        if (n < NPACK) {
            if (k < XS)       v = (n < HS3) ? Wiou[k * HS3 + n] : Wf[k * HS + (n - HS3)];
            else if (k == XS) v = (n < HS3) ? biou[n] : bf[n - HS3];
        }
        g_Bw[idx] = __float2half_rn(v);
    } else if (idx < NW + NU) {
        int j = idx - NW;
        int n = j / KPU, k = j - n * KPU;
        float v = 0.0f;
        if (k < HS && n < NPACK) v = (n < HS3) ? Uiou[k * HS3 + n] : Uf[k * HS + (n - HS3)];
        g_Bu[j] = __float2half_rn(v);
    }
}

__global__ void k_prep_emb(const float* __restrict__ emb)
{
    int idx = blockIdx.x * blockDim.x + threadIdx.x;
    if (idx >= VPAD * KPW) return;
    int r = idx / KPW, k = idx - r * KPW;
    float v = 0.0f;
    if (r < VOCAB) {
        if (k < XS)       v = emb[(size_t)r * XS + k];
        else if (k == XS) v = 1.0f;          // bias slot
    }
    g_Ef[idx] = __float2half_rn(v);
}

__global__ void k_zeropads()
{
    int idx = blockIdx.x * blockDim.x + threadIdx.x;
    const int T1 = (NNODES + 128) * 10;
    const int T2 = (LEAVES / 2) * 10;
    if (idx < T1) {
        int r = idx / 10, k = HS + idx % 10;
        g_hf[(size_t)r * KPU + k] = __float2half_rn(0.0f);
    } else if (idx < T1 + T2) {
        int j = idx - T1;
        int r = j / 10, k = HS + j % 10;
        g_sf[(size_t)r * KPU + k] = __float2half_rn(0.0f);
    }
}

__global__ void k_bar_reset() { g_bar = 0; }

// ---------------- cp.async(4-stage) + ldmatrix fp16 mma.sync GEMM core ------------
#define PLANEB 10240                  // 128 rows * 80B
#define STAGEB 20480                  // 2 planes (A, B)
#define NSTAGE 4
#define SMEMT  (NSTAGE * STAGEB)      // 81920

__device__ __forceinline__ void gemm_core(
    int bx, int by, char* smem,
    const __half* __restrict__ A, int M, int Kpad,
    const __half* __restrict__ B, int Nact, __half* __restrict__ C, int ldc)
{
    const uint32_t sb = smem_u32(smem);
    const int tid  = threadIdx.x;
    const int lane = tid & 31;
    const int wid  = tid >> 5;
    const int row0 = by << 7;
    const int col0 = bx << 7;
    const int m0 = (wid & 3) << 5;
    const int n0 = (wid >> 2) << 6;
    const int g   = lane >> 2;
    const int tig = lane & 3;

    const int lr   = lane & 7;
    const uint32_t aOff = (uint32_t)(m0 + lr + (((lane >> 3) & 1) << 3)) * 80
                        + (uint32_t)((lane >> 4) << 4);
    const uint32_t bOff = (uint32_t)(n0 + lr + ((lane >> 4) << 3)) * 80
                        + (uint32_t)(((lane >> 3) & 1) << 4);

    const char* pA = (const char*)(A + (size_t)row0 * Kpad);
    const char* pB = (const char*)(B + (size_t)col0 * Kpad);

    const int r_ld = tid >> 1;
    const int sg2  = (tid & 1) << 1;

    float d[2][8][4];
    #pragma unroll
    for (int mb = 0; mb < 2; mb++)
        #pragma unroll
        for (int nb = 0; nb < 8; nb++)
            #pragma unroll
            for (int q = 0; q < 4; q++) d[mb][nb][q] = 0.0f;

    auto load_chunk = [&](int kb, int st) {
        uint32_t dbase = sb + st * STAGEB + r_ld * 80 + sg2 * 16;
        size_t   soff  = ((size_t)r_ld * Kpad + kb + sg2 * 8) * 2;
        CP16(dbase,               pA + soff);
        CP16(dbase + 16,          pA + soff + 16);
        CP16(dbase + PLANEB,      pB + soff);
        CP16(dbase + PLANEB + 16, pB + soff + 16);
    };

    const int chunks = Kpad >> 5;
    #pragma unroll
    for (int s = 0; s < NSTAGE - 1; s++) {
        load_chunk(s << 5, s);
        CP_COMMIT();
    }

    for (int c = 0; c < chunks; c++) {
        CP_WAITG2();
        __syncthreads();

        const uint32_t sbase = sb + (c & (NSTAGE - 1)) * STAGEB;

        #pragma unroll
        for (int ks = 0; ks < 2; ks++) {
            uint32_t ah[2][4];
            #pragma unroll
            for (int mb = 0; mb < 2; mb++) {
                uint32_t aoff = sbase + aOff + mb * (16 * 80) + ks * 32;
                LDSM4(ah[mb][0], ah[mb][1], ah[mb][2], ah[mb][3], aoff);
            }
            #pragma unroll
            for (int pr = 0; pr < 4; pr++) {
                uint32_t boff = sbase + PLANEB + bOff + pr * (16 * 80) + ks * 32;
                uint32_t bh[4];
                LDSM4(bh[0], bh[1], bh[2], bh[3], boff);
                #pragma unroll
                for (int mb = 0; mb < 2; mb++) {
                    MMA_F16(d[mb][2 * pr],     ah[mb][0], ah[mb][1], ah[mb][2], ah[mb][3], bh[0], bh[1]);
                    MMA_F16(d[mb][2 * pr + 1], ah[mb][0], ah[mb][1], ah[mb][2], ah[mb][3], bh[2], bh[3]);
                }
            }
        }
        __syncthreads();
        if (c + NSTAGE - 1 < chunks)
            load_chunk((c + NSTAGE - 1) << 5, (c + NSTAGE - 1) & (NSTAGE - 1));
        CP_COMMIT();
    }

    #pragma unroll
    for (int mb = 0; mb < 2; mb++) {
        int gr = row0 + m0 + mb * 16 + g;
        #pragma unroll
        for (int nb = 0; nb < 8; nb++) {
            int gc = col0 + n0 + nb * 8 + tig * 2;
            if (gc < Nact) {
                if (gr < M)
                    *(__half2*)(C + (size_t)gr * ldc + gc) =
                        __floats2half2_rn(d[mb][nb][0], d[mb][nb][1]);
                if (gr + 8 < M)
                    *(__half2*)(C + (size_t)(gr + 8) * ldc + gc) =
                        __floats2half2_rn(d[mb][nb][2], d[mb][nb][3]);
            }
        }
    }
}

// vocab precompute wrapper
__global__ __launch_bounds__(256, 2)
void k_mma_g(const __half* __restrict__ A, int M, int Kpad,
             const __half* __restrict__ B, int Nact, __half* __restrict__ C, int ldc)
{
    extern __shared__ char smem[];
    gemm_core(blockIdx.x, blockIdx.y, smem, A, M, Kpad, B, Nact, C, ldc);
}

// merged per-level wrapper: seg0 = psum @ U_iou; seg1 = h @ U_f
__global__ __launch_bounds__(256, 2)
void k_mma_lvl(const __half* __restrict__ A1, int M1, __half* __restrict__ C1,
               const __half* __restrict__ A2, int M2, __half* __restrict__ C2,
               const __half* __restrict__ Bu, int nby1)
{
    extern __shared__ char smem[];
    int b = blockIdx.x;
    int total1 = nby1 << 2;
    if (b < total1) {
        gemm_core(b & 3, b >> 2, smem, A1, M1, KPU, Bu, HS3, C1, HS3);
    } else {
        b -= total1;
        gemm_core(b & 1, b >> 1, smem, A2, M2, KPU, Bu + (size_t)HS3 * KPU, HS, C2, HS);
    }
}

// ---------------- leaf level: gates + fused pair-sum + fused out ------------------
__global__ __launch_bounds__(320)
void k_leaf(const int* __restrict__ xid,
            const float* __restrict__ Wout, const float* __restrict__ bout,
            float* __restrict__ out)
{
    __shared__ float sh[300];
    const int t = threadIdx.x;
    const int b = blockIdx.x;
    if (t < 300) {
        int child = (t >= 150);
        int j = t - child * 150;
        int i = 2 * b + child;
        int n = (LEAVES - 1) + i;
        const __half* ew = g_EW + (size_t)xid[n] * NPACK;
        float iv = __half2float(ew[j]);
        float ov = __half2float(ew[HS + j]);
        float uv = __half2float(ew[2 * HS + j]);
        float cv = sig_f(iv) * tanh_f(uv);
        float hv = sig_f(ov) * tanh_f(cv);
        g_c[(size_t)n * HS + j] = cv;
        g_hf[(size_t)n * KPU + j] = __float2half_rn(hv);
        sh[t] = hv;
    }
    __syncthreads();
    if (t < 150) {
        float s = sh[t] + sh[150 + t];
        g_sf[(size_t)b * KPU + t] = __float2half_rn(s);
    }
    int w = t >> 5, lane = t & 31;
    if (w < 10) {
        int nd = w / 5, q = w - nd * 5;
        float a = 0.f;
        for (int j = lane; j < HS; j += 32)
            a = fmaf(sh[nd * HS + j], Wout[j * NC + q], a);
        #pragma unroll
        for (int off = 16; off; off >>= 1) a += __shfl_xor_sync(0xffffffffu, a, off);
        if (lane == 0) {
            int n = (LEAVES - 1) + 2 * b + nd;
            out[(size_t)n * NC + q] = a + bout[q];
        }
    }
}

// ---------------- internal-level combine + fused pair-sum + fused out -------------
__global__ __launch_bounds__(320)
void k_combine(int s, int cs, const int* __restrict__ xid,
               const float* __restrict__ Wout, const float* __restrict__ bout,
               float* __restrict__ out)
{
    __shared__ float sh[300];
    const int t = threadIdx.x;
    const int b = blockIdx.x;
    if (t < 300) {
        int child = (t >= 150);
        int j = t - child * 150;
        int k = 2 * b + child;
        int p = s + k;
        const __half* ew  = g_EW + (size_t)xid[p] * NPACK;
        const __half* hio = g_hiou + (size_t)k * HS3;
        float iv = __half2float(ew[j])          + __half2float(hio[j]);
        float ov = __half2float(ew[HS + j])     + __half2float(hio[HS + j]);
        float uv = __half2float(ew[2 * HS + j]) + __half2float(hio[2 * HS + j]);
        float xf = __half2float(ew[HS3 + j]);
        float fl = sig_f(xf + __half2float(g_hUf[(size_t)(2 * k) * HS + j]));
        float fr = sig_f(xf + __half2float(g_hUf[(size_t)(2 * k + 1) * HS + j]));
        float cl = g_c[(size_t)(cs + 2 * k) * HS + j];
        float cr = g_c[(size_t)(cs + 2 * k + 1) * HS + j];
        float cv = sig_f(iv) * tanh_f(uv) + fl * cl + fr * cr;
        float hv = sig_f(ov) * tanh_f(cv);
        g_c[(size_t)p * HS + j] = cv;
        g_hf[(size_t)p * KPU + j] = __float2half_rn(hv);
        sh[t] = hv;
    }
    __syncthreads();
    if (t < 150) {
        float sum = sh[t] + sh[150 + t];
        g_sf[(size_t)b * KPU + t] = __float2half_rn(sum);
    }
    int w = t >> 5, lane = t & 31;
    if (w < 10) {
        int nd = w / 5, q = w - nd * 5;
        float a = 0.f;
        for (int j = lane; j < HS; j += 32)
            a = fmaf(sh[nd * HS + j], Wout[j * NC + q], a);
        #pragma unroll
        for (int off = 16; off; off >>= 1) a += __shfl_xor_sync(0xffffffffu, a, off);
        if (lane == 0) {
            int p = s + 2 * b + nd;
            out[(size_t)p * NC + q] = a + bout[q];
        }
    }
}

// ---------------- persistent upper tree (levels LTOP..0, fp32 GEMV) ---------------
__global__ __launch_bounds__(256, 4)
void k_upper(const float* __restrict__ Uiou, const float* __restrict__ Uf,
             const int* __restrict__ xid,
             const float* __restrict__ Wout, const float* __restrict__ bout,
             float* __restrict__ out)
{
    __shared__ float hl_[HS], hr_[HS], hs_[HS], ho_[HS];
    __shared__ float io_[HS3], fl_[HS], fr_[HS];
    const int t = threadIdx.x;
    const int k = blockIdx.x;
    int target = 0;

    for (int lvl = LTOP; lvl >= 0; lvl--) {
        const int M  = 1 << lvl;
        const int s  = M - 1;
        const int cs = 2 * M - 1;
        if (k < M) {
            const int p = s + k;
            for (int j = t; j < HS; j += 256) {
                float hl = __half2float(__ldcg(&g_hf[(size_t)(cs + 2 * k) * KPU + j]));
                float hr = __half2float(__ldcg(&g_hf[(size_t)(cs + 2 * k + 1) * KPU + j]));
                hl_[j] = hl; hr_[j] = hr; hs_[j] = hl + hr;
            }
            __syncthreads();

            for (int j = t; j < HS3; j += 256) {
                float a = 0.0f;
                #pragma unroll 5
                for (int kk = 0; kk < HS; kk++) a = fmaf(hs_[kk], Uiou[kk * HS3 + j], a);
                io_[j] = a;
            }
            for (int j = t; j < HS; j += 256) {
                float al = 0.0f, ar = 0.0f;
                #pragma unroll 5
                for (int kk = 0; kk < HS; kk++) {
                    float u = Uf[kk * HS + j];
                    al = fmaf(hl_[kk], u, al);
                    ar = fmaf(hr_[kk], u, ar);
                }
                fl_[j] = al; fr_[j] = ar;
            }
            __syncthreads();

            if (t < HS) {
                int j = t;
                const __half* ew = g_EW + (size_t)xid[p] * NPACK;
                float iv = __half2float(ew[j]) + io_[j];
                float ov = __half2float(ew[HS + j]) + io_[HS + j];
                float uv = __half2float(ew[2 * HS + j]) + io_[2 * HS + j];
                float xf = __half2float(ew[HS3 + j]);
                float fl = sig_f(xf + fl_[j]);
                float fr = sig_f(xf + fr_[j]);
                float cl = __ldcg(&g_c[(size_t)(cs + 2 * k) * HS + j]);
                float cr = __ldcg(&g_c[(size_t)(cs + 2 * k + 1) * HS + j]);
                float cv = sig_f(iv) * tanh_f(uv) + fl * cl + fr * cr;
                float hv = sig_f(ov) * tanh_f(cv);
                g_c[(size_t)p * HS + j] = cv;
                g_hf[(size_t)p * KPU + j] = __float2half_rn(hv);
                ho_[j] = hv;
            }
            __syncthreads();
            int w = t >> 5, lane = t & 31;
            if (w < NC) {
                float a = 0.f;
                for (int j = lane; j < HS; j += 32)
                    a = fmaf(ho_[j], Wout[j * NC + w], a);
                #pragma unroll
                for (int off = 16; off; off >>= 1) a += __shfl_xor_sync(0xffffffffu, a, off);
                if (lane == 0) out[(size_t)p * NC + w] = a + bout[w];
            }
        }
        if (lvl == 0) break;
        __threadfence();
        __syncthreads();
        target += (int)gridDim.x;
        if (t == 0) {
            atomicAdd(&g_bar, 1);
            while (*((volatile int*)&g_bar) < target) { }
        }
        __syncthreads();
    }
}

// ---------------- host orchestration ---------------------------------------------
extern "C" void kernel_launch(void* const* d_in, const int* in_sizes, int n_in,
                              void* d_out, int out_size)
{
    (void)in_sizes; (void)n_in; (void)out_size;
    const int*   xid  = (const int*)d_in[0];
    const float* emb  = (const float*)d_in[1];
    const float* Wiou = (const float*)d_in[2];
    const float* Uiou = (const float*)d_in[3];
    const float* biou = (const float*)d_in[4];
    const float* Wf   = (const float*)d_in[5];
    const float* Uf   = (const float*)d_in[6];
    const float* bf   = (const float*)d_in[7];
    const float* Wout = (const float*)d_in[8];
    const float* bout = (const float*)d_in[9];
    float* out = (float*)d_out;

    __half *pEW, *pHiou, *pHUf, *pEf, *pBw, *pBu, *pHf, *pSf;
    cudaGetSymbolAddress((void**)&pEW,   g_EW);
    cudaGetSymbolAddress((void**)&pHiou, g_hiou);
    cudaGetSymbolAddress((void**)&pHUf,  g_hUf);
    cudaGetSymbolAddress((void**)&pEf,   g_Ef);
    cudaGetSymbolAddress((void**)&pBw,   g_Bw);
    cudaGetSymbolAddress((void**)&pBu,   g_Bu);
    cudaGetSymbolAddress((void**)&pHf,   g_hf);
    cudaGetSymbolAddress((void**)&pSf,   g_sf);

    cudaFuncSetAttribute(k_mma_g,   cudaFuncAttributeMaxDynamicSharedMemorySize, SMEMT);
    cudaFuncSetAttribute(k_mma_lvl, cudaFuncAttributeMaxDynamicSharedMemorySize, SMEMT);

    const dim3 thr(256);
    k_prep_w<<<(NBROW * KPW + NBROW * KPU + 255) / 256, thr>>>(Wiou, Wf, Uiou, Uf, biou, bf);
    k_prep_emb<<<(VPAD * KPW + 255) / 256, thr>>>(emb);
    {
        int zt = (NNODES + 128) * 10 + (LEAVES / 2) * 10;
        k_zeropads<<<(zt + 255) / 256, thr>>>();
    }

    // Vocab precompute (bias folded): g_EW = [emb|1] @ [W|b]^T
    k_mma_g<<<dim3(5, VPAD / 128), thr, SMEMT>>>(pEf, VOCAB, KPW, pBw, NPACK, pEW, NPACK);

    // Leaf level.
    k_leaf<<<LEAVES / 2, 320>>>(xid, Wout, bout, out);

    // Levels 17..7: 4-stage pipelined HMMA GEMM + combine.
    for (int lvl = DEPTH - 1; lvl >= LVL_SMALL; lvl--) {
        int M  = 1 << lvl;
        int s  = M - 1;
        int cs = 2 * M - 1;
        int nby1 = (M + 127) / 128;
        int nby2 = (2 * M + 127) / 128;
        int nblk = 4 * nby1 + 2 * nby2;
        k_mma_lvl<<<nblk, thr, SMEMT>>>(
            pSf, M, pHiou,
            pHf + (size_t)cs * KPU, 2 * M, pHUf,
            pBu, nby1);
        k_combine<<<M / 2, 320>>>(s, cs, xid, Wout, bout, out);
    }

    // Levels 6..0: single persistent kernel with software grid barrier.
    k_bar_reset<<<1, 1>>>();
    k_upper<<<UGRID, thr>>>(Uiou, Uf, xid, Wout, bout, out);
}

// round 11
// speedup vs baseline: 1.3125x; 1.1541x over previous
#include <cuda_runtime.h>
#include <cuda_fp16.h>
#include <cstdint>
#include <cstddef>

#define VOCAB   50000
#define VPAD    50048        // 391 * 128
#define XS      300
#define HS      150
#define HS3     450
#define NPACK   600          // [iou(450) | f(150)]
#define NBROW   768
#define NC      5
#define DEPTH   18
#define NNODES  524287
#define LEAVES  262144
#define KPW     320
#define KPU     160
#define LVL_SMALL 7          // levels >= this use the HMMA GEMM path
#define LTOP      6          // persistent kernel covers levels LTOP..0
#define UGRID     64

// ---------------- static device scratch ------------------------------------------
__device__ __half g_EW[(size_t)VOCAB * NPACK];            // [emb|1] @ [W|b] (bias folded)
__device__ __half g_hiou[(size_t)(LEAVES / 2) * HS3];
__device__ __half g_hUf[(size_t)LEAVES * HS];
__device__ float  g_c[(size_t)NNODES * HS];
__device__ __half g_hf[(size_t)(NNODES + 128) * KPU];
__device__ __half g_sf[(size_t)(LEAVES / 2) * KPU];
__device__ __half g_Ef[(size_t)VPAD * KPW];
__device__ __half g_Bw[(size_t)NBROW * KPW];
__device__ __half g_Bu[(size_t)NBROW * KPU];
__device__ int    g_bar;

// ---------------- helpers ---------------------------------------------------------
__device__ __forceinline__ uint32_t smem_u32(const void* p) {
    uint32_t a;
    asm("{ .reg .u64 t; cvta.to.shared.u64 t, %1; cvt.u32.u64 %0, t; }" : "=r"(a) : "l"(p));
    return a;
}
#define CP16(dst, src) \
    asm volatile("cp.async.cg.shared.global [%0], [%1], 16;" :: "r"(dst), "l"(src))
#define CP_COMMIT() asm volatile("cp.async.commit_group;" ::: "memory")
#define CP_WAITG2() asm volatile("cp.async.wait_group 2;" ::: "memory")
#define LDSM4(r0, r1, r2, r3, addr)                                               \
    asm volatile("ldmatrix.sync.aligned.m8n8.x4.shared.b16 {%0,%1,%2,%3}, [%4];"  \
                 : "=r"(r0), "=r"(r1), "=r"(r2), "=r"(r3) : "r"(addr))
#define MMA_F16(d, a0, a1, a2, a3, b0, b1)                                       \
    asm volatile("mma.sync.aligned.m16n8k16.row.col.f32.f16.f16.f32 "            \
                 "{%0,%1,%2,%3},{%4,%5,%6,%7},{%8,%9},{%0,%1,%2,%3};"            \
                 : "+f"(d[0]), "+f"(d[1]), "+f"(d[2]), "+f"(d[3])                \
                 : "r"(a0), "r"(a1), "r"(a2), "r"(a3), "r"(b0), "r"(b1))

// ---------------- FMA-only activations -------------------------------------------
__device__ __forceinline__ float sig_f(float x) {
    float ax = fabsf(x);
    if (ax > 1.0f) return 1.0f / (1.0f + __expf(-x));
    float x2 = x * x;
    float p = fmaf(x2, 2.1357958e-5f, -2.1081349e-4f);
    p = fmaf(x2, p, 2.0833333e-3f);
    p = fmaf(x2, p, -2.0833333e-2f);
    p = fmaf(x2, p, 0.25f);
    return fmaf(x, p, 0.5f);
}
__device__ __forceinline__ float tanh_f(float x) {
    float ax = fabsf(x);
    if (ax > 0.55f) {
        float t = __expf(-2.0f * ax);
        float r = __fdividef(1.0f - t, 1.0f + t);
        return x < 0.0f ? -r : r;
    }
    float x2 = x * x;
    float p = fmaf(x2, 2.1869488e-2f, -5.3968254e-2f);
    p = fmaf(x2, p, 1.3333333e-1f);
    p = fmaf(x2, p, -3.3333333e-1f);
    p = fmaf(x2, p, 1.0f);
    return x * p;
}

// ---------------- prep kernels ----------------------------------------------------
__global__ void k_prep_w(const float* __restrict__ Wiou, const float* __restrict__ Wf,
                         const float* __restrict__ Uiou, const float* __restrict__ Uf,
                         const float* __restrict__ biou, const float* __restrict__ bf)
{
    int idx = blockIdx.x * blockDim.x + threadIdx.x;
    const int NW = NBROW * KPW;
    const int NU = NBROW * KPU;
    if (idx < NW) {
        int n = idx / KPW, k = idx - n * KPW;
        float v = 0.0f;
        if (n < NPACK) {
            if (k < XS)       v = (n < HS3) ? Wiou[k * HS3 + n] : Wf[k * HS + (n - HS3)];
            else if (k == XS) v = (n < HS3) ? biou[n] : bf[n - HS3];
        }
        g_Bw[idx] = __float2half_rn(v);
    } else if (idx < NW + NU) {
        int j = idx - NW;
        int n = j / KPU, k = j - n * KPU;
        float v = 0.0f;
        if (k < HS && n < NPACK) v = (n < HS3) ? Uiou[k * HS3 + n] : Uf[k * HS + (n - HS3)];
        g_Bu[j] = __float2half_rn(v);
    }
}

__global__ void k_prep_emb(const float* __restrict__ emb)
{
    int idx = blockIdx.x * blockDim.x + threadIdx.x;
    if (idx >= VPAD * KPW) return;
    int r = idx / KPW, k = idx - r * KPW;
    float v = 0.0f;
    if (r < VOCAB) {
        if (k < XS)       v = emb[(size_t)r * XS + k];
        else if (k == XS) v = 1.0f;
    }
    g_Ef[idx] = __float2half_rn(v);
}

__global__ void k_zeropads()
{
    int idx = blockIdx.x * blockDim.x + threadIdx.x;
    const int T1 = (NNODES + 128) * 10;
    const int T2 = (LEAVES / 2) * 10;
    if (idx < T1) {
        int r = idx / 10, k = HS + idx % 10;
        g_hf[(size_t)r * KPU + k] = __float2half_rn(0.0f);
    } else if (idx < T1 + T2) {
        int j = idx - T1;
        int r = j / 10, k = HS + j % 10;
        g_sf[(size_t)r * KPU + k] = __float2half_rn(0.0f);
    }
}

__global__ void k_bar_reset() { g_bar = 0; }

// ---------------- cp.async(4-stage) + ldmatrix fp16 mma.sync GEMM core ------------
// Template NT = CTA column-tile width: 128 (8 warps 32x64) or 32 (8 warps 16x32).
#define APLANE 10240                  // 128 rows * 80B
#define NSTAGE 4
#define SMEMT  (NSTAGE * (APLANE + 128 * 80))   // NT=128 worst case: 81920

template <int NT>
__device__ __forceinline__ void gemm_core(
    int col0, int by, char* smem,
    const __half* __restrict__ A, int M, int Kpad,
    const __half* __restrict__ B, int Nact, __half* __restrict__ C, int ldc)
{
    constexpr int BPLANE = NT * 80;
    constexpr int STAGE  = APLANE + BPLANE;
    constexpr int MB = (NT == 128) ? 2 : 1;     // 32- or 16-row warp m-tile
    constexpr int NBW = (NT == 128) ? 8 : 4;    // n8 blocks per warp
    constexpr int PRMAX = NBW / 2;

    const uint32_t sb = smem_u32(smem);
    const int tid  = threadIdx.x;
    const int lane = tid & 31;
    const int wid  = tid >> 5;
    const int row0 = by << 7;
    const int m0 = (NT == 128) ? ((wid & 3) << 5) : (wid << 4);
    const int n0 = (NT == 128) ? ((wid >> 2) << 6) : 0;
    const int g   = lane >> 2;
    const int tig = lane & 3;

    const int lr   = lane & 7;
    const uint32_t aOff = (uint32_t)(m0 + lr + (((lane >> 3) & 1) << 3)) * 80
                        + (uint32_t)((lane >> 4) << 4);
    const uint32_t bOff = (uint32_t)(n0 + lr + ((lane >> 4) << 3)) * 80
                        + (uint32_t)(((lane >> 3) & 1) << 4);

    const char* pA = (const char*)(A + (size_t)row0 * Kpad);
    const char* pB = (const char*)(B + (size_t)col0 * Kpad);

    const int r_ld = tid >> 1;
    const int sg2  = (tid & 1) << 1;

    float d[MB][NBW][4];
    #pragma unroll
    for (int mb = 0; mb < MB; mb++)
        #pragma unroll
        for (int nb = 0; nb < NBW; nb++)
            #pragma unroll
            for (int q = 0; q < 4; q++) d[mb][nb][q] = 0.0f;

    auto load_chunk = [&](int kb, int st) {
        uint32_t dbase = sb + st * STAGE + r_ld * 80 + sg2 * 16;
        size_t   soff  = ((size_t)r_ld * Kpad + kb + sg2 * 8) * 2;
        CP16(dbase,      pA + soff);
        CP16(dbase + 16, pA + soff + 16);
        if (NT == 128) {
            CP16(dbase + APLANE,      pB + soff);
            CP16(dbase + APLANE + 16, pB + soff + 16);
        } else if (tid < 64) {
            // B: 32 rows, threads 0..63 (2 per row)
            uint32_t db = sb + st * STAGE + APLANE + r_ld * 80 + sg2 * 16;
            size_t   sofb = ((size_t)r_ld * Kpad + kb + sg2 * 8) * 2;
            CP16(db,      pB + sofb);
            CP16(db + 16, pB + sofb + 16);
        }
    };

    const int chunks = Kpad >> 5;
    #pragma unroll
    for (int s = 0; s < NSTAGE - 1; s++) {
        load_chunk(s << 5, s);
        CP_COMMIT();
    }

    for (int c = 0; c < chunks; c++) {
        CP_WAITG2();
        __syncthreads();

        const uint32_t sbase = sb + (c & (NSTAGE - 1)) * STAGE;

        #pragma unroll
        for (int ks = 0; ks < 2; ks++) {
            uint32_t ah[MB][4];
            #pragma unroll
            for (int mb = 0; mb < MB; mb++) {
                uint32_t aoff = sbase + aOff + mb * (16 * 80) + ks * 32;
                LDSM4(ah[mb][0], ah[mb][1], ah[mb][2], ah[mb][3], aoff);
            }
            #pragma unroll
            for (int pr = 0; pr < PRMAX; pr++) {
                uint32_t boff = sbase + APLANE + bOff + pr * (16 * 80) + ks * 32;
                uint32_t bh[4];
                LDSM4(bh[0], bh[1], bh[2], bh[3], boff);
                #pragma unroll
                for (int mb = 0; mb < MB; mb++) {
                    MMA_F16(d[mb][2 * pr],     ah[mb][0], ah[mb][1], ah[mb][2], ah[mb][3], bh[0], bh[1]);
                    MMA_F16(d[mb][2 * pr + 1], ah[mb][0], ah[mb][1], ah[mb][2], ah[mb][3], bh[2], bh[3]);
                }
            }
        }
        __syncthreads();
        if (c + NSTAGE - 1 < chunks)
            load_chunk((c + NSTAGE - 1) << 5, (c + NSTAGE - 1) & (NSTAGE - 1));
        CP_COMMIT();
    }

    #pragma unroll
    for (int mb = 0; mb < MB; mb++) {
        int gr = row0 + m0 + mb * 16 + g;
        #pragma unroll
        for (int nb = 0; nb < NBW; nb++) {
            int gc = col0 + n0 + nb * 8 + tig * 2;
            if (gc < Nact) {
                if (gr < M)
                    *(__half2*)(C + (size_t)gr * ldc + gc) =
                        __floats2half2_rn(d[mb][nb][0], d[mb][nb][1]);
                if (gr + 8 < M)
                    *(__half2*)(C + (size_t)(gr + 8) * ldc + gc) =
                        __floats2half2_rn(d[mb][nb][2], d[mb][nb][3]);
            }
        }
    }
}

// vocab precompute wrapper
__global__ __launch_bounds__(256, 2)
void k_mma_g(const __half* __restrict__ A, int M, int Kpad,
             const __half* __restrict__ B, int Nact, __half* __restrict__ C, int ldc)
{
    extern __shared__ char smem[];
    gemm_core<128>(blockIdx.x << 7, blockIdx.y, smem, A, M, Kpad, B, Nact, C, ldc);
}

// merged per-level wrapper: seg1 = psum @ U_iou (N=450, 4 wide tiles);
// seg2 = h @ U_f (N=150: one 128-tile + one 32-tile)
__global__ __launch_bounds__(256, 2)
void k_mma_lvl(const __half* __restrict__ A1, int M1, __half* __restrict__ C1,
               const __half* __restrict__ A2, int M2, __half* __restrict__ C2,
               const __half* __restrict__ Bu, int nby1, int nby2)
{
    extern __shared__ char smem[];
    int b = blockIdx.x;
    int t1 = nby1 << 2;
    if (b < t1) {
        gemm_core<128>((b & 3) << 7, b >> 2, smem, A1, M1, KPU, Bu, HS3, C1, HS3);
    } else if (b < t1 + nby2) {
        b -= t1;
        gemm_core<128>(0, b, smem, A2, M2, KPU, Bu + (size_t)HS3 * KPU, HS, C2, HS);
    } else {
        b -= t1 + nby2;
        gemm_core<32>(128, b, smem, A2, M2, KPU, Bu + (size_t)HS3 * KPU, HS, C2, HS);
    }
}

// ---------------- leaf: gates + psum + out, 4 leaves/block, half2 -----------------
__global__ __launch_bounds__(320)
void k_leaf(const int* __restrict__ xid,
            const float* __restrict__ Wout, const float* __restrict__ bout,
            float* __restrict__ out)
{
    __shared__ float sh[4 * 152];
    const int t = threadIdx.x;
    const int b = blockIdx.x;
    if (t < 300) {
        int q  = t / 75;
        int j2 = t - q * 75;
        int j  = j2 << 1;
        int n  = (LEAVES - 1) + 4 * b + q;
        const __half2* ew2 = (const __half2*)(g_EW + (size_t)xid[n] * NPACK);
        float2 iv = __half22float2(ew2[j2]);
        float2 ov = __half22float2(ew2[75 + j2]);
        float2 uv = __half22float2(ew2[150 + j2]);
        float cvx = sig_f(iv.x) * tanh_f(uv.x);
        float cvy = sig_f(iv.y) * tanh_f(uv.y);
        float hvx = sig_f(ov.x) * tanh_f(cvx);
        float hvy = sig_f(ov.y) * tanh_f(cvy);
        *(float2*)(g_c + (size_t)n * HS + j) = make_float2(cvx, cvy);
        *(__half2*)(g_hf + (size_t)n * KPU + j) = __floats2half2_rn(hvx, hvy);
        sh[q * 152 + j]     = hvx;
        sh[q * 152 + j + 1] = hvy;
    }
    __syncthreads();
    if (t < 150) {
        int q01 = t / 75;
        int j   = (t - q01 * 75) << 1;
        float sx = sh[(2 * q01) * 152 + j]     + sh[(2 * q01 + 1) * 152 + j];
        float sy = sh[(2 * q01) * 152 + j + 1] + sh[(2 * q01 + 1) * 152 + j + 1];
        *(__half2*)(g_sf + (size_t)(2 * b + q01) * KPU + j) = __floats2half2_rn(sx, sy);
    }
    int w = t >> 5, lane = t & 31;
    if (w < 10) {
        int q = w % 5, pg = w / 5;
        #pragma unroll
        for (int pp = 0; pp < 2; pp++) {
            int slot = 2 * pg + pp;
            float a = 0.f;
            for (int j = lane; j < HS; j += 32)
                a = fmaf(sh[slot * 152 + j], Wout[j * NC + q], a);
            #pragma unroll
            for (int off = 16; off; off >>= 1) a += __shfl_xor_sync(0xffffffffu, a, off);
            if (lane == 0) {
                int n = (LEAVES - 1) + 4 * b + slot;
                out[(size_t)n * NC + q] = a + bout[q];
            }
        }
    }
}

// ---------------- combine: gates + psum + out, 4 parents/block, half2 -------------
__global__ __launch_bounds__(320)
void k_combine(int s, int cs, const int* __restrict__ xid,
               const float* __restrict__ Wout, const float* __restrict__ bout,
               float* __restrict__ out)
{
    __shared__ float sh[4 * 152];
    const int t = threadIdx.x;
    const int b = blockIdx.x;
    if (t < 300) {
        int q  = t / 75;
        int j2 = t - q * 75;
        int j  = j2 << 1;
        int k  = 4 * b + q;
        int p  = s + k;
        const __half2* ew2  = (const __half2*)(g_EW + (size_t)xid[p] * NPACK);
        const __half2* hio2 = (const __half2*)(g_hiou + (size_t)k * HS3);
        float2 iv = __half22float2(ew2[j2]);
        float2 ov = __half22float2(ew2[75 + j2]);
        float2 uv = __half22float2(ew2[150 + j2]);
        float2 xf = __half22float2(ew2[225 + j2]);
        float2 hi0 = __half22float2(hio2[j2]);
        float2 hi1 = __half22float2(hio2[75 + j2]);
        float2 hi2v = __half22float2(hio2[150 + j2]);
        iv.x += hi0.x; iv.y += hi0.y;
        ov.x += hi1.x; ov.y += hi1.y;
        uv.x += hi2v.x; uv.y += hi2v.y;
        float2 ufL = __half22float2(*(const __half2*)(g_hUf + (size_t)(2 * k) * HS + j));
        float2 ufR = __half22float2(*(const __half2*)(g_hUf + (size_t)(2 * k + 1) * HS + j));
        float2 cl = *(const float2*)(g_c + (size_t)(cs + 2 * k) * HS + j);
        float2 cr = *(const float2*)(g_c + (size_t)(cs + 2 * k + 1) * HS + j);
        float flx = sig_f(xf.x + ufL.x), fly = sig_f(xf.y + ufL.y);
        float frx = sig_f(xf.x + ufR.x), fry = sig_f(xf.y + ufR.y);
        float cvx = sig_f(iv.x) * tanh_f(uv.x) + flx * cl.x + frx * cr.x;
        float cvy = sig_f(iv.y) * tanh_f(uv.y) + fly * cl.y + fry * cr.y;
        float hvx = sig_f(ov.x) * tanh_f(cvx);
        float hvy = sig_f(ov.y) * tanh_f(cvy);
        *(float2*)(g_c + (size_t)p * HS + j) = make_float2(cvx, cvy);
        *(__half2*)(g_hf + (size_t)p * KPU + j) = __floats2half2_rn(hvx, hvy);
        sh[q * 152 + j]     = hvx;
        sh[q * 152 + j + 1] = hvy;
    }
    __syncthreads();
    if (t < 150) {
        int q01 = t / 75;
        int j   = (t - q01 * 75) << 1;
        float sx = sh[(2 * q01) * 152 + j]     + sh[(2 * q01 + 1) * 152 + j];
        float sy = sh[(2 * q01) * 152 + j + 1] + sh[(2 * q01 + 1) * 152 + j + 1];
        *(__half2*)(g_sf + (size_t)(2 * b + q01) * KPU + j) = __floats2half2_rn(sx, sy);
    }
    int w = t >> 5, lane = t & 31;
    if (w < 10) {
        int q = w % 5, pg = w / 5;
        #pragma unroll
        for (int pp = 0; pp < 2; pp++) {
            int slot = 2 * pg + pp;
            float a = 0.f;
            for (int j = lane; j < HS; j += 32)
                a = fmaf(sh[slot * 152 + j], Wout[j * NC + q], a);
            #pragma unroll
            for (int off = 16; off; off >>= 1) a += __shfl_xor_sync(0xffffffffu, a, off);
            if (lane == 0) {
                int p = s + 4 * b + slot;
                out[(size_t)p * NC + q] = a + bout[q];
            }
        }
    }
}

// ---------------- persistent upper tree (levels LTOP..0, fp32 GEMV) ---------------
__global__ __launch_bounds__(256, 4)
void k_upper(const float* __restrict__ Uiou, const float* __restrict__ Uf,
             const int* __restrict__ xid,
             const float* __restrict__ Wout, const float* __restrict__ bout,
             float* __restrict__ out)
{
    __shared__ float hl_[HS], hr_[HS], hs_[HS], ho_[HS];
    __shared__ float io_[HS3], fl_[HS], fr_[HS];
    const int t = threadIdx.x;
    const int k = blockIdx.x;
    int target = 0;

    for (int lvl = LTOP; lvl >= 0; lvl--) {
        const int M  = 1 << lvl;
        const int s  = M - 1;
        const int cs = 2 * M - 1;
        if (k < M) {
            const int p = s + k;
            for (int j = t; j < HS; j += 256) {
                float hl = __half2float(__ldcg(&g_hf[(size_t)(cs + 2 * k) * KPU + j]));
                float hr = __half2float(__ldcg(&g_hf[(size_t)(cs + 2 * k + 1) * KPU + j]));
                hl_[j] = hl; hr_[j] = hr; hs_[j] = hl + hr;
            }
            __syncthreads();

            for (int j = t; j < HS3; j += 256) {
                float a = 0.0f;
                #pragma unroll 5
                for (int kk = 0; kk < HS; kk++) a = fmaf(hs_[kk], Uiou[kk * HS3 + j], a);
                io_[j] = a;
            }
            for (int j = t; j < HS; j += 256) {
                float al = 0.0f, ar = 0.0f;
                #pragma unroll 5
                for (int kk = 0; kk < HS; kk++) {
                    float u = Uf[kk * HS + j];
                    al = fmaf(hl_[kk], u, al);
                    ar = fmaf(hr_[kk], u, ar);
                }
                fl_[j] = al; fr_[j] = ar;
            }
            __syncthreads();

            if (t < HS) {
                int j = t;
                const __half* ew = g_EW + (size_t)xid[p] * NPACK;
                float iv = __half2float(ew[j]) + io_[j];
                float ov = __half2float(ew[HS + j]) + io_[HS + j];
                float uv = __half2float(ew[2 * HS + j]) + io_[2 * HS + j];
                float xf = __half2float(ew[HS3 + j]);
                float fl = sig_f(xf + fl_[j]);
                float fr = sig_f(xf + fr_[j]);
                float cl = __ldcg(&g_c[(size_t)(cs + 2 * k) * HS + j]);
                float cr = __ldcg(&g_c[(size_t)(cs + 2 * k + 1) * HS + j]);
                float cv = sig_f(iv) * tanh_f(uv) + fl * cl + fr * cr;
                float hv = sig_f(ov) * tanh_f(cv);
                g_c[(size_t)p * HS + j] = cv;
                g_hf[(size_t)p * KPU + j] = __float2half_rn(hv);
                ho_[j] = hv;
            }
            __syncthreads();
            int w = t >> 5, lane = t & 31;
            if (w < NC) {
                float a = 0.f;
                for (int j = lane; j < HS; j += 32)
                    a = fmaf(ho_[j], Wout[j * NC + w], a);
                #pragma unroll
                for (int off = 16; off; off >>= 1) a += __shfl_xor_sync(0xffffffffu, a, off);
                if (lane == 0) out[(size_t)p * NC + w] = a + bout[w];
            }
        }
        if (lvl == 0) break;
        __threadfence();
        __syncthreads();
        target += (int)gridDim.x;
        if (t == 0) {
            atomicAdd(&g_bar, 1);
            while (*((volatile int*)&g_bar) < target) { }
        }
        __syncthreads();
    }
}

// ---------------- host orchestration ---------------------------------------------
extern "C" void kernel_launch(void* const* d_in, const int* in_sizes, int n_in,
                              void* d_out, int out_size)
{
    (void)in_sizes; (void)n_in; (void)out_size;
    const int*   xid  = (const int*)d_in[0];
    const float* emb  = (const float*)d_in[1];
    const float* Wiou = (const float*)d_in[2];
    const float* Uiou = (const float*)d_in[3];
    const float* biou = (const float*)d_in[4];
    const float* Wf   = (const float*)d_in[5];
    const float* Uf   = (const float*)d_in[6];
    const float* bf   = (const float*)d_in[7];
    const float* Wout = (const float*)d_in[8];
    const float* bout = (const float*)d_in[9];
    float* out = (float*)d_out;

    __half *pEW, *pHiou, *pHUf, *pEf, *pBw, *pBu, *pHf, *pSf;
    cudaGetSymbolAddress((void**)&pEW,   g_EW);
    cudaGetSymbolAddress((void**)&pHiou, g_hiou);
    cudaGetSymbolAddress((void**)&pHUf,  g_hUf);
    cudaGetSymbolAddress((void**)&pEf,   g_Ef);
    cudaGetSymbolAddress((void**)&pBw,   g_Bw);
    cudaGetSymbolAddress((void**)&pBu,   g_Bu);
    cudaGetSymbolAddress((void**)&pHf,   g_hf);
    cudaGetSymbolAddress((void**)&pSf,   g_sf);

    cudaFuncSetAttribute(k_mma_g,   cudaFuncAttributeMaxDynamicSharedMemorySize, SMEMT);
    cudaFuncSetAttribute(k_mma_lvl, cudaFuncAttributeMaxDynamicSharedMemorySize, SMEMT);

    const dim3 thr(256);
    k_prep_w<<<(NBROW * KPW + NBROW * KPU + 255) / 256, thr>>>(Wiou, Wf, Uiou, Uf, biou, bf);
    k_prep_emb<<<(VPAD * KPW + 255) / 256, thr>>>(emb);
    {
        int zt = (NNODES + 128) * 10 + (LEAVES / 2) * 10;
        k_zeropads<<<(zt + 255) / 256, thr>>>();
    }

    // Vocab precompute (bias folded): g_EW = [emb|1] @ [W|b]^T
    k_mma_g<<<dim3(5, VPAD / 128), thr, SMEMT>>>(pEf, VOCAB, KPW, pBw, NPACK, pEW, NPACK);

    // Leaf level (4 leaves per block).
    k_leaf<<<LEAVES / 4, 320>>>(xid, Wout, bout, out);

    // Levels 17..7: pipelined HMMA GEMM (seg2 narrow second tile) + combine.
    for (int lvl = DEPTH - 1; lvl >= LVL_SMALL; lvl--) {
        int M  = 1 << lvl;
        int s  = M - 1;
        int cs = 2 * M - 1;
        int nby1 = (M + 127) / 128;
        int nby2 = (2 * M + 127) / 128;
        int nblk = 4 * nby1 + 2 * nby2;
        k_mma_lvl<<<nblk, thr, SMEMT>>>(
            pSf, M, pHiou,
            pHf + (size_t)cs * KPU, 2 * M, pHUf,
            pBu, nby1, nby2);
        k_combine<<<M / 4, 320>>>(s, cs, xid, Wout, bout, out);
    }

    // Levels 6..0: persistent kernel.
    k_bar_reset<<<1, 1>>>();
    k_upper<<<UGRID, thr>>>(Uiou, Uf, xid, Wout, bout, out);
}